// round 1
// baseline (speedup 1.0000x reference)
#include <cuda_runtime.h>
#include <math.h>

#define BB 2
#define NN 2048
#define CC 768
#define HH 12
#define HD 64
#define ROWS (BB*NN)          // 4096
#define C3 (3*CC)             // 2304

// Scratch (static device globals — no allocation)
__device__ float g_qkv[(size_t)ROWS * C3];   // [B*N, 3C]  (37.7 MB)
__device__ float g_att[(size_t)ROWS * CC];   // [B*N, C]   (12.6 MB)

// ---------------------------------------------------------------------------
// Tiled fp32 GEMM: C[M,Nn] = A[M,K] @ B[K,Nn] (+bias). BM=BN=64, BK=16,
// 256 threads, 4x4 microtile per thread. All dims divide the tiles exactly.
// ---------------------------------------------------------------------------
template<bool HAS_BIAS>
__global__ __launch_bounds__(256) void gemm64(const float* __restrict__ A,
                                              const float* __restrict__ Bm,
                                              const float* __restrict__ bias,
                                              float* __restrict__ Cm,
                                              int M, int K, int Nn)
{
    __shared__ float As[16][65];   // padded to kill store conflicts
    __shared__ float Bs[16][64];

    const int tid = threadIdx.x;
    const int tx  = tid & 15;        // 0..15  -> col group
    const int ty  = tid >> 4;        // 0..15  -> row group
    const int row0 = blockIdx.y * 64;
    const int col0 = blockIdx.x * 64;

    // load-index decomposition
    const int ar  = tid >> 2;        // 0..63 : A tile row
    const int ac4 = tid & 3;         // 0..3  : A float4 col group (BK=16)
    const int br  = tid >> 4;        // 0..15 : B tile row (k)
    const int bc4 = tid & 15;        // 0..15 : B float4 col group

    float acc[4][4] = {};

    for (int k0 = 0; k0 < K; k0 += 16) {
        float4 av = *(const float4*)(A  + (size_t)(row0 + ar) * K  + k0 + ac4 * 4);
        float4 bv = *(const float4*)(Bm + (size_t)(k0 + br) * Nn + col0 + bc4 * 4);
        As[ac4*4+0][ar] = av.x;
        As[ac4*4+1][ar] = av.y;
        As[ac4*4+2][ar] = av.z;
        As[ac4*4+3][ar] = av.w;
        *(float4*)&Bs[br][bc4*4] = bv;
        __syncthreads();

        #pragma unroll
        for (int k = 0; k < 16; k++) {
            float ra[4], rb[4];
            #pragma unroll
            for (int i = 0; i < 4; i++) ra[i] = As[k][ty*4 + i];
            #pragma unroll
            for (int j = 0; j < 4; j++) rb[j] = Bs[k][tx*4 + j];
            #pragma unroll
            for (int i = 0; i < 4; i++)
                #pragma unroll
                for (int j = 0; j < 4; j++)
                    acc[i][j] += ra[i] * rb[j];
        }
        __syncthreads();
    }

    #pragma unroll
    for (int i = 0; i < 4; i++) {
        int r = row0 + ty*4 + i;
        #pragma unroll
        for (int j = 0; j < 4; j++) {
            int c = col0 + tx*4 + j;
            float v = acc[i][j];
            if (HAS_BIAS) v += bias[c];
            Cm[(size_t)r * Nn + c] = v;
        }
    }
}

// ---------------------------------------------------------------------------
// Flash-style attention. 1 thread = 1 query row. Block = 128 threads = 128
// queries. grid = (N/128, B*H). q (scaled) and o live in registers (64+64),
// KV staged in smem in 32-key tiles, online softmax per tile.
// qkv layout per row (len 3C): Q at h*64, K at 768+h*64, V at 1536+h*64.
// ---------------------------------------------------------------------------
__global__ __launch_bounds__(128) void attn_kernel(const float* __restrict__ qkv,
                                                   float* __restrict__ out)
{
    const int bh = blockIdx.y;
    const int b  = bh / HH;
    const int h  = bh % HH;
    const int qn = blockIdx.x * 128 + threadIdx.x;   // query index in [0,N)

    const float scale = 0.125f;                      // HD^-0.5
    const float* base = qkv + (size_t)b * NN * C3;

    // load q (scale folded in)
    float q[HD];
    const float4* qp = (const float4*)(base + (size_t)qn * C3 + h * HD);
    #pragma unroll
    for (int d4 = 0; d4 < 16; d4++) {
        float4 v = qp[d4];
        q[d4*4+0] = v.x * scale;
        q[d4*4+1] = v.y * scale;
        q[d4*4+2] = v.z * scale;
        q[d4*4+3] = v.w * scale;
    }

    float o[HD];
    #pragma unroll
    for (int d = 0; d < HD; d++) o[d] = 0.f;
    float m = -INFINITY, l = 0.f;

    __shared__ float Ks[32][HD];
    __shared__ float Vs[32][HD];

    for (int kt = 0; kt < NN; kt += 32) {
        __syncthreads();   // previous tile fully consumed
        // cooperative load: 32 rows x 64 floats x2 tensors; 512 float4 each
        #pragma unroll
        for (int i = 0; i < 4; i++) {
            int idx = threadIdx.x + i * 128;    // 0..511
            int j   = idx >> 4;                 // key row 0..31
            int c4  = idx & 15;                 // float4 col
            const float* krow = base + (size_t)(kt + j) * C3 + CC + h * HD;
            const float* vrow = base + (size_t)(kt + j) * C3 + 2*CC + h * HD;
            ((float4*)Ks[j])[c4] = *(const float4*)(krow + c4 * 4);
            ((float4*)Vs[j])[c4] = *(const float4*)(vrow + c4 * 4);
        }
        __syncthreads();

        // scores for this tile
        float s[32];
        float tm = -INFINITY;
        #pragma unroll
        for (int j = 0; j < 32; j++) {
            const float4* kr = (const float4*)Ks[j];
            float a0 = 0.f, a1 = 0.f, a2 = 0.f, a3 = 0.f;
            #pragma unroll
            for (int d4 = 0; d4 < 16; d4++) {
                float4 kv = kr[d4];
                a0 += q[d4*4+0] * kv.x;
                a1 += q[d4*4+1] * kv.y;
                a2 += q[d4*4+2] * kv.z;
                a3 += q[d4*4+3] * kv.w;
            }
            s[j] = (a0 + a1) + (a2 + a3);
            tm = fmaxf(tm, s[j]);
        }

        // online softmax update
        float m_new = fmaxf(m, tm);
        float corr  = __expf(m - m_new);   // exp(-inf) = 0 on first tile
        l *= corr;
        #pragma unroll
        for (int d = 0; d < HD; d++) o[d] *= corr;

        #pragma unroll
        for (int j = 0; j < 32; j++) {
            float p = __expf(s[j] - m_new);
            l += p;
            const float4* vr = (const float4*)Vs[j];
            #pragma unroll
            for (int d4 = 0; d4 < 16; d4++) {
                float4 vv = vr[d4];
                o[d4*4+0] += p * vv.x;
                o[d4*4+1] += p * vv.y;
                o[d4*4+2] += p * vv.z;
                o[d4*4+3] += p * vv.w;
            }
        }
        m = m_new;
    }

    const float inv = 1.f / l;
    float* op = out + ((size_t)b * NN + qn) * CC + h * HD;
    #pragma unroll
    for (int d4 = 0; d4 < 16; d4++) {
        float4 v;
        v.x = o[d4*4+0] * inv;
        v.y = o[d4*4+1] * inv;
        v.z = o[d4*4+2] * inv;
        v.w = o[d4*4+3] * inv;
        ((float4*)op)[d4] = v;
    }
}

// ---------------------------------------------------------------------------
extern "C" void kernel_launch(void* const* d_in, const int* in_sizes, int n_in,
                              void* d_out, int out_size)
{
    const float* x      = (const float*)d_in[0];   // [B,N,C]
    const float* w_qkv  = (const float*)d_in[1];   // [C,3C]
    const float* w_proj = (const float*)d_in[2];   // [C,C]
    const float* b_proj = (const float*)d_in[3];   // [C]
    float* out = (float*)d_out;                    // [B,N,C]

    float* qkv = nullptr;
    float* att = nullptr;
    cudaGetSymbolAddress((void**)&qkv, g_qkv);
    cudaGetSymbolAddress((void**)&att, g_att);

    // 1) QKV projection: [4096,768] @ [768,2304]
    {
        dim3 grid(C3 / 64, ROWS / 64);
        gemm64<false><<<grid, 256>>>(x, w_qkv, nullptr, qkv, ROWS, CC, C3);
    }
    // 2) attention
    {
        dim3 grid(NN / 128, BB * HH);
        attn_kernel<<<grid, 128>>>(qkv, att);
    }
    // 3) output projection + bias: [4096,768] @ [768,768] + b
    {
        dim3 grid(CC / 64, ROWS / 64);
        gemm64<true><<<grid, 256>>>(att, w_proj, b_proj, out, ROWS, CC, CC);
    }
}

// round 4
// speedup vs baseline: 4.1345x; 4.1345x over previous
#include <cuda_runtime.h>
#include <cstdint>
#include <math.h>

#define BB 2
#define NN 2048
#define CC 768
#define HH 12
#define HD 64
#define ROWS (BB*NN)          // 4096
#define C3 (3*CC)             // 2304

// Scratch (static device globals — no allocation)
__device__ float g_qkv[(size_t)ROWS * C3];   // [B*N, 3C]
__device__ float g_att[(size_t)ROWS * CC];   // [B*N, C]

// ---------------------------------------------------------------------------
// helpers
// ---------------------------------------------------------------------------
__device__ __forceinline__ uint32_t f2tf32(float x) {
    uint32_t r;
    asm("cvt.rna.tf32.f32 %0, %1;" : "=r"(r) : "f"(x));
    return r;
}
__device__ __forceinline__ void cvt4(uint32_t* d, float4 v) {
    d[0] = f2tf32(v.x); d[1] = f2tf32(v.y); d[2] = f2tf32(v.z); d[3] = f2tf32(v.w);
}
// D += A(16x8) * B(8x8), tf32 inputs (bit pattern in uint), fp32 accum
__device__ __forceinline__ void mma8(float* d, const uint32_t* a, const uint32_t* b) {
    asm volatile(
        "mma.sync.aligned.m16n8k8.row.col.f32.tf32.tf32.f32 "
        "{%0,%1,%2,%3}, {%4,%5,%6,%7}, {%8,%9}, {%0,%1,%2,%3};\n"
        : "+f"(d[0]), "+f"(d[1]), "+f"(d[2]), "+f"(d[3])
        : "r"(a[0]), "r"(a[1]), "r"(a[2]), "r"(a[3]), "r"(b[0]), "r"(b[1]));
}

// ---------------------------------------------------------------------------
// tf32 warp-MMA GEMM: C[M,Nn] = A[M,K] @ W[K,Nn] (+bias)
// BM=128, BN=128, BK=32. 256 threads / 8 warps; warp tile 32x64.
// ---------------------------------------------------------------------------
#define APAD 36   // 32 + 4
#define BPAD 132  // 128 + 4
template<bool HAS_BIAS>
__global__ __launch_bounds__(256) void gemm_mma(const float* __restrict__ A,
                                                const float* __restrict__ W,
                                                const float* __restrict__ bias,
                                                float* __restrict__ Cm,
                                                int M, int K, int Nn)
{
    __shared__ uint32_t As[128 * APAD];
    __shared__ uint32_t Bs[32 * BPAD];

    const int tid  = threadIdx.x;
    const int wid  = tid >> 5;
    const int lane = tid & 31;
    const int wr   = wid & 3;         // warp row (4)  -> 32 rows
    const int wc   = wid >> 2;        // warp col (2)  -> 64 cols
    const int row0 = blockIdx.y * 128;
    const int col0 = blockIdx.x * 128;
    const int lr   = lane >> 2;       // 0..7
    const int lc   = lane & 3;        // 0..3

    float acc[2][8][4];
    #pragma unroll
    for (int i = 0; i < 2; i++)
        #pragma unroll
        for (int j = 0; j < 8; j++)
            #pragma unroll
            for (int v = 0; v < 4; v++) acc[i][j][v] = 0.f;

    for (int k0 = 0; k0 < K; k0 += 32) {
        __syncthreads();
        // A tile 128x32 (1024 float4)
        #pragma unroll
        for (int t = 0; t < 4; t++) {
            int idx = tid + t * 256;
            int r = idx >> 3, c4 = idx & 7;
            float4 v = *(const float4*)(A + (size_t)(row0 + r) * K + k0 + c4 * 4);
            cvt4(&As[r * APAD + c4 * 4], v);
        }
        // B tile 32x128 (1024 float4)
        #pragma unroll
        for (int t = 0; t < 4; t++) {
            int idx = tid + t * 256;
            int k = idx >> 5, c4 = idx & 31;
            float4 v = *(const float4*)(W + (size_t)(k0 + k) * Nn + col0 + c4 * 4);
            cvt4(&Bs[k * BPAD + c4 * 4], v);
        }
        __syncthreads();

        #pragma unroll
        for (int kk = 0; kk < 4; kk++) {   // k-step of 8
            const int ks = kk * 8;
            uint32_t af[2][4];
            #pragma unroll
            for (int mt = 0; mt < 2; mt++) {
                int r = wr * 32 + mt * 16 + lr;
                af[mt][0] = As[r * APAD + ks + lc];
                af[mt][1] = As[(r + 8) * APAD + ks + lc];
                af[mt][2] = As[r * APAD + ks + lc + 4];
                af[mt][3] = As[(r + 8) * APAD + ks + lc + 4];
            }
            #pragma unroll
            for (int nt = 0; nt < 8; nt++) {
                int n = wc * 64 + nt * 8 + lr;
                uint32_t bf[2];
                bf[0] = Bs[(ks + lc) * BPAD + n];
                bf[1] = Bs[(ks + lc + 4) * BPAD + n];
                mma8(acc[0][nt], af[0], bf);
                mma8(acc[1][nt], af[1], bf);
            }
        }
    }

    // epilogue
    #pragma unroll
    for (int mt = 0; mt < 2; mt++) {
        int r = row0 + wr * 32 + mt * 16 + lr;
        #pragma unroll
        for (int nt = 0; nt < 8; nt++) {
            int c = col0 + wc * 64 + nt * 8 + 2 * lc;
            float2 v0 = make_float2(acc[mt][nt][0], acc[mt][nt][1]);
            float2 v1 = make_float2(acc[mt][nt][2], acc[mt][nt][3]);
            if (HAS_BIAS) {
                float2 bb = *(const float2*)(bias + c);
                v0.x += bb.x; v0.y += bb.y; v1.x += bb.x; v1.y += bb.y;
            }
            *(float2*)(Cm + (size_t)r * Nn + c) = v0;
            *(float2*)(Cm + (size_t)(r + 8) * Nn + c) = v1;
        }
    }
}

// ---------------------------------------------------------------------------
// Flash attention with tf32 mma.sync. 256 threads / 8 warps; each warp owns
// 16 query rows (128 q per CTA). Key tiles of 64. Online softmax.
// qkv row layout (len 3C): Q at h*64, K at 768+h*64, V at 1536+h*64.
// dyn smem: Ks[64][68] | Vs[64][68] | Pw[8][16][68]   (floats)
// ---------------------------------------------------------------------------
#define KVP 68
#define SM_K  0
#define SM_V  (64 * KVP)
#define SM_P  (128 * KVP)
#define ATTN_SMEM_BYTES ((SM_P + 8 * 16 * KVP) * 4)

__global__ __launch_bounds__(256) void attn_mma(const float* __restrict__ qkv,
                                                float* __restrict__ out)
{
    extern __shared__ float sm[];
    const int tid  = threadIdx.x;
    const int wid  = tid >> 5;
    const int lane = tid & 31;
    const int lr   = lane >> 2;   // 0..7
    const int lc   = lane & 3;    // 0..3

    const int bh = blockIdx.y;
    const int b  = bh / HH;
    const int h  = bh % HH;
    const int q0 = blockIdx.x * 128;                 // CTA query base
    const float* base = qkv + (size_t)b * NN * C3;
    float* Pw = sm + SM_P + wid * (16 * KVP);

    // ---- stage Q tile [128][64] into Ks/Vs region, then grab fragments ----
    // 128 rows x 16 float4 = 2048 float4  (FIX: was 1024, leaving dims 32-63 garbage)
    #pragma unroll
    for (int t = 0; t < 8; t++) {
        int idx = tid + t * 256;          // 0..2047
        int r = idx >> 4, c4 = idx & 15;
        float4 v = *(const float4*)(base + (size_t)(q0 + r) * C3 + h * HD + c4 * 4);
        *(float4*)(sm + r * KVP + c4 * 4) = v;
    }
    __syncthreads();

    uint32_t qf[8][4];
    {
        const float scale = 0.125f;
        int r = wid * 16 + lr;
        #pragma unroll
        for (int kk = 0; kk < 8; kk++) {
            qf[kk][0] = f2tf32(sm[r * KVP + kk * 8 + lc] * scale);
            qf[kk][1] = f2tf32(sm[(r + 8) * KVP + kk * 8 + lc] * scale);
            qf[kk][2] = f2tf32(sm[r * KVP + kk * 8 + lc + 4] * scale);
            qf[kk][3] = f2tf32(sm[(r + 8) * KVP + kk * 8 + lc + 4] * scale);
        }
    }

    float of[8][4];
    #pragma unroll
    for (int j = 0; j < 8; j++)
        #pragma unroll
        for (int v = 0; v < 4; v++) of[j][v] = 0.f;
    float m0 = -INFINITY, m1 = -INFINITY, l0 = 0.f, l1 = 0.f;

    const uint32_t* Ks = (const uint32_t*)(sm + SM_K);
    const uint32_t* Vs = (const uint32_t*)(sm + SM_V);

    for (int kt = 0; kt < NN; kt += 64) {
        __syncthreads();   // previous tile consumed (and Q staging read done)
        // load K,V tiles 64x64 (tf32-converted): 1024 float4 each
        #pragma unroll
        for (int t = 0; t < 4; t++) {
            int idx = tid + t * 256;      // 0..1023
            int j = idx >> 4, c4 = idx & 15;
            const float* krow = base + (size_t)(kt + j) * C3 + CC + h * HD;
            const float* vrow = base + (size_t)(kt + j) * C3 + 2 * CC + h * HD;
            cvt4((uint32_t*)(sm + SM_K + j * KVP) + c4 * 4, *(const float4*)(krow + c4 * 4));
            cvt4((uint32_t*)(sm + SM_V + j * KVP) + c4 * 4, *(const float4*)(vrow + c4 * 4));
        }
        __syncthreads();

        // S = Q K^T  : 8 n-tiles (keys) x 8 k-steps (dims)
        float sf[8][4];
        #pragma unroll
        for (int nt = 0; nt < 8; nt++) {
            #pragma unroll
            for (int v = 0; v < 4; v++) sf[nt][v] = 0.f;
            #pragma unroll
            for (int kk = 0; kk < 8; kk++) {
                uint32_t bf[2];
                bf[0] = Ks[(nt * 8 + lr) * KVP + kk * 8 + lc];
                bf[1] = Ks[(nt * 8 + lr) * KVP + kk * 8 + lc + 4];
                mma8(sf[nt], qf[kk], bf);
            }
        }

        // online softmax (rows r0 = regs 0,1 ; r1 = regs 2,3)
        float tm0 = -INFINITY, tm1 = -INFINITY;
        #pragma unroll
        for (int nt = 0; nt < 8; nt++) {
            tm0 = fmaxf(tm0, fmaxf(sf[nt][0], sf[nt][1]));
            tm1 = fmaxf(tm1, fmaxf(sf[nt][2], sf[nt][3]));
        }
        tm0 = fmaxf(tm0, __shfl_xor_sync(0xffffffff, tm0, 1));
        tm0 = fmaxf(tm0, __shfl_xor_sync(0xffffffff, tm0, 2));
        tm1 = fmaxf(tm1, __shfl_xor_sync(0xffffffff, tm1, 1));
        tm1 = fmaxf(tm1, __shfl_xor_sync(0xffffffff, tm1, 2));

        float mn0 = fmaxf(m0, tm0), mn1 = fmaxf(m1, tm1);
        float cr0 = __expf(m0 - mn0), cr1 = __expf(m1 - mn1);

        float rs0 = 0.f, rs1 = 0.f;
        #pragma unroll
        for (int nt = 0; nt < 8; nt++) {
            float p00 = __expf(sf[nt][0] - mn0);
            float p01 = __expf(sf[nt][1] - mn0);
            float p10 = __expf(sf[nt][2] - mn1);
            float p11 = __expf(sf[nt][3] - mn1);
            rs0 += p00 + p01;
            rs1 += p10 + p11;
            // store P (tf32) to per-warp smem
            int c = nt * 8 + 2 * lc;
            *(uint32_t*)&Pw[lr * KVP + c]       = f2tf32(p00);
            *(uint32_t*)&Pw[lr * KVP + c + 1]   = f2tf32(p01);
            *(uint32_t*)&Pw[(lr + 8) * KVP + c]     = f2tf32(p10);
            *(uint32_t*)&Pw[(lr + 8) * KVP + c + 1] = f2tf32(p11);
        }
        rs0 += __shfl_xor_sync(0xffffffff, rs0, 1);
        rs0 += __shfl_xor_sync(0xffffffff, rs0, 2);
        rs1 += __shfl_xor_sync(0xffffffff, rs1, 1);
        rs1 += __shfl_xor_sync(0xffffffff, rs1, 2);
        l0 = l0 * cr0 + rs0;
        l1 = l1 * cr1 + rs1;
        m0 = mn0; m1 = mn1;

        // rescale o
        #pragma unroll
        for (int dt = 0; dt < 8; dt++) {
            of[dt][0] *= cr0; of[dt][1] *= cr0;
            of[dt][2] *= cr1; of[dt][3] *= cr1;
        }

        __syncwarp();
        // o += P V : A = P[16x64] (k=keys), B = V[64x64]
        const uint32_t* Pu = (const uint32_t*)Pw;
        #pragma unroll
        for (int kk = 0; kk < 8; kk++) {
            uint32_t pf[4];
            pf[0] = Pu[lr * KVP + kk * 8 + lc];
            pf[1] = Pu[(lr + 8) * KVP + kk * 8 + lc];
            pf[2] = Pu[lr * KVP + kk * 8 + lc + 4];
            pf[3] = Pu[(lr + 8) * KVP + kk * 8 + lc + 4];
            #pragma unroll
            for (int dt = 0; dt < 8; dt++) {
                uint32_t bf[2];
                bf[0] = Vs[(kk * 8 + lc) * KVP + dt * 8 + lr];
                bf[1] = Vs[(kk * 8 + lc + 4) * KVP + dt * 8 + lr];
                mma8(of[dt], pf, bf);
            }
        }
        __syncwarp();
    }

    // write out
    const float i0 = 1.f / l0, i1 = 1.f / l1;
    const int qr = q0 + wid * 16 + lr;
    #pragma unroll
    for (int dt = 0; dt < 8; dt++) {
        int c = h * HD + dt * 8 + 2 * lc;
        *(float2*)(out + ((size_t)b * NN + qr) * CC + c) =
            make_float2(of[dt][0] * i0, of[dt][1] * i0);
        *(float2*)(out + ((size_t)b * NN + qr + 8) * CC + c) =
            make_float2(of[dt][2] * i1, of[dt][3] * i1);
    }
}

// ---------------------------------------------------------------------------
extern "C" void kernel_launch(void* const* d_in, const int* in_sizes, int n_in,
                              void* d_out, int out_size)
{
    const float* x      = (const float*)d_in[0];   // [B,N,C]
    const float* w_qkv  = (const float*)d_in[1];   // [C,3C]
    const float* w_proj = (const float*)d_in[2];   // [C,C]
    const float* b_proj = (const float*)d_in[3];   // [C]
    float* out = (float*)d_out;                    // [B,N,C]

    float* qkv = nullptr;
    float* att = nullptr;
    cudaGetSymbolAddress((void**)&qkv, g_qkv);
    cudaGetSymbolAddress((void**)&att, g_att);

    cudaFuncSetAttribute(attn_mma, cudaFuncAttributeMaxDynamicSharedMemorySize,
                         ATTN_SMEM_BYTES);

    // 1) QKV projection: [4096,768] @ [768,2304]
    {
        dim3 grid(C3 / 128, ROWS / 128);
        gemm_mma<false><<<grid, 256>>>(x, w_qkv, nullptr, qkv, ROWS, CC, C3);
    }
    // 2) attention
    {
        dim3 grid(NN / 128, BB * HH);
        attn_mma<<<grid, 256, ATTN_SMEM_BYTES>>>(qkv, att);
    }
    // 3) output projection + bias
    {
        dim3 grid(CC / 128, ROWS / 128);
        gemm_mma<true><<<grid, 256>>>(att, w_proj, b_proj, out, ROWS, CC, CC);
    }
}

// round 5
// speedup vs baseline: 4.6173x; 1.1168x over previous
#include <cuda_runtime.h>
#include <cstdint>
#include <math.h>

#define BB 2
#define NN 2048
#define CC 768
#define HH 12
#define HD 64
#define ROWS (BB*NN)          // 4096
#define C3 (3*CC)             // 2304

// Scratch (static device globals — no allocation)
__device__ float g_qkv[(size_t)ROWS * C3];   // [B*N, 3C] (tf32-rounded)
__device__ float g_att[(size_t)ROWS * CC];   // [B*N, C]  (tf32-rounded)
__device__ float g_xt [(size_t)ROWS * CC];   // tf32(x)
__device__ float g_wqt[(size_t)CC * C3];     // tf32(w_qkv)
__device__ float g_wpt[(size_t)CC * CC];     // tf32(w_proj)

// ---------------------------------------------------------------------------
// helpers
// ---------------------------------------------------------------------------
__device__ __forceinline__ uint32_t smem_u32(const void* p) {
    uint32_t a;
    asm("{ .reg .u64 t; cvta.to.shared.u64 t, %1; cvt.u32.u64 %0, t; }"
        : "=r"(a) : "l"(p));
    return a;
}
__device__ __forceinline__ uint32_t f2tf32(float x) {
    uint32_t r;
    asm("cvt.rna.tf32.f32 %0, %1;" : "=r"(r) : "f"(x));
    return r;
}
__device__ __forceinline__ void cp16(uint32_t dst, const void* src) {
    asm volatile("cp.async.cg.shared.global [%0], [%1], 16;" :: "r"(dst), "l"(src));
}
__device__ __forceinline__ void cp_commit() {
    asm volatile("cp.async.commit_group;" ::: "memory");
}
template<int N> __device__ __forceinline__ void cp_wait() {
    asm volatile("cp.async.wait_group %0;" :: "n"(N) : "memory");
}
// D += A(16x8) * B(8x8), tf32 inputs (bit pattern in uint), fp32 accum
__device__ __forceinline__ void mma8(float* d, const uint32_t* a, const uint32_t* b) {
    asm volatile(
        "mma.sync.aligned.m16n8k8.row.col.f32.tf32.tf32.f32 "
        "{%0,%1,%2,%3}, {%4,%5,%6,%7}, {%8,%9}, {%0,%1,%2,%3};\n"
        : "+f"(d[0]), "+f"(d[1]), "+f"(d[2]), "+f"(d[3])
        : "r"(a[0]), "r"(a[1]), "r"(a[2]), "r"(a[3]), "r"(b[0]), "r"(b[1]));
}

// ---------------------------------------------------------------------------
// Pre-pass: round x, w_qkv, w_proj to tf32 (rna), stored as fp32 bits.
// ---------------------------------------------------------------------------
#define N1 ((ROWS*CC)/4)
#define N2 ((CC*C3)/4)
#define N3 ((CC*CC)/4)
__global__ void cvt_pass(const float* __restrict__ x,
                         const float* __restrict__ wq,
                         const float* __restrict__ wp)
{
    int idx = blockIdx.x * 256 + threadIdx.x;
    const float4* s; float4* d;
    if (idx < N1)                { s = (const float4*)x  + idx;       d = (float4*)g_xt  + idx; }
    else if (idx < N1 + N2)      { s = (const float4*)wq + (idx-N1);  d = (float4*)g_wqt + (idx-N1); }
    else if (idx < N1 + N2 + N3) { s = (const float4*)wp + (idx-N1-N2); d = (float4*)g_wpt + (idx-N1-N2); }
    else return;
    float4 v = *s;
    v.x = __uint_as_float(f2tf32(v.x));
    v.y = __uint_as_float(f2tf32(v.y));
    v.z = __uint_as_float(f2tf32(v.z));
    v.w = __uint_as_float(f2tf32(v.w));
    *d = v;
}

// ---------------------------------------------------------------------------
// tf32 warp-MMA GEMM, cp.async double-buffered.
// C[M,Nn] = A[M,K] @ W[K,Nn] (+bias). BM=BN=128, BK=32. 8 warps, 32x64/warp.
// Inputs must already be tf32-rounded. If CVT_OUT, output is tf32-rounded.
// ---------------------------------------------------------------------------
#define APAD 36                 // 32+4 : (lr*4+lc)&31 distinct
#define BPAD 136                // 128+8: (lc*8+lr)&31 distinct
#define AWORDS (128*APAD)       // 4608
#define BWORDS (32*BPAD)        // 4352
#define BUFW   (AWORDS+BWORDS)  // 8960
#define GEMM_SMEM_BYTES (2*BUFW*4)   // 71680

template<bool HAS_BIAS, bool CVT_OUT>
__global__ __launch_bounds__(256) void gemm_cp(const float* __restrict__ A,
                                               const float* __restrict__ W,
                                               const float* __restrict__ bias,
                                               float* __restrict__ Cm,
                                               int M, int K, int Nn)
{
    extern __shared__ uint32_t smg[];
    const uint32_t sb = smem_u32(smg);
    const int tid  = threadIdx.x;
    const int wid  = tid >> 5;
    const int lane = tid & 31;
    const int wr   = wid & 3;
    const int wc   = wid >> 2;
    const int lr   = lane >> 2;
    const int lc   = lane & 3;
    const int row0 = blockIdx.y * 128;
    const int col0 = blockIdx.x * 128;

    float acc[2][8][4];
    #pragma unroll
    for (int i = 0; i < 2; i++)
        #pragma unroll
        for (int j = 0; j < 8; j++)
            #pragma unroll
            for (int v = 0; v < 4; v++) acc[i][j][v] = 0.f;

    // decomposed load indices
    const int ar  = tid >> 3,  ac4 = tid & 7;    // A: 128 rows x 8 f4-cols, 4 iters
    const int bk  = tid >> 5,  bc4 = tid & 31;   // B: 32 rows x 32 f4-cols, 4 iters

    #define ISSUE_TILE(ch, buf) do {                                              \
        const int _k0 = (ch) * 32;                                                \
        uint32_t _ab = sb + (buf) * (BUFW * 4);                                   \
        uint32_t _bb = _ab + AWORDS * 4;                                          \
        _Pragma("unroll")                                                         \
        for (int t = 0; t < 4; t++) {                                             \
            int r = ar + t * 32;                                                  \
            cp16(_ab + (r * APAD + ac4 * 4) * 4,                                  \
                 A + (size_t)(row0 + r) * K + _k0 + ac4 * 4);                     \
        }                                                                         \
        _Pragma("unroll")                                                         \
        for (int t = 0; t < 4; t++) {                                             \
            int k = bk + t * 8;                                                   \
            cp16(_bb + (k * BPAD + bc4 * 4) * 4,                                  \
                 W + (size_t)(_k0 + k) * Nn + col0 + bc4 * 4);                    \
        }                                                                         \
    } while (0)

    const int nch = K >> 5;
    ISSUE_TILE(0, 0); cp_commit();

    for (int ch = 0; ch < nch; ch++) {
        if (ch + 1 < nch) {
            ISSUE_TILE(ch + 1, (ch + 1) & 1); cp_commit();
            cp_wait<1>();
        } else {
            cp_wait<0>();
        }
        __syncthreads();

        const uint32_t* As = smg + (ch & 1) * BUFW;
        const uint32_t* Bs = As + AWORDS;

        #pragma unroll
        for (int kk = 0; kk < 4; kk++) {
            const int ks = kk * 8;
            uint32_t af[2][4];
            #pragma unroll
            for (int mt = 0; mt < 2; mt++) {
                int r = wr * 32 + mt * 16 + lr;
                af[mt][0] = As[r * APAD + ks + lc];
                af[mt][1] = As[(r + 8) * APAD + ks + lc];
                af[mt][2] = As[r * APAD + ks + lc + 4];
                af[mt][3] = As[(r + 8) * APAD + ks + lc + 4];
            }
            #pragma unroll
            for (int nt = 0; nt < 8; nt++) {
                int n = wc * 64 + nt * 8 + lr;
                uint32_t bf[2];
                bf[0] = Bs[(ks + lc) * BPAD + n];
                bf[1] = Bs[(ks + lc + 4) * BPAD + n];
                mma8(acc[0][nt], af[0], bf);
                mma8(acc[1][nt], af[1], bf);
            }
        }
        __syncthreads();
    }
    #undef ISSUE_TILE

    // epilogue
    #pragma unroll
    for (int mt = 0; mt < 2; mt++) {
        int r = row0 + wr * 32 + mt * 16 + lr;
        #pragma unroll
        for (int nt = 0; nt < 8; nt++) {
            int c = col0 + wc * 64 + nt * 8 + 2 * lc;
            float2 v0 = make_float2(acc[mt][nt][0], acc[mt][nt][1]);
            float2 v1 = make_float2(acc[mt][nt][2], acc[mt][nt][3]);
            if (HAS_BIAS) {
                float2 bb = *(const float2*)(bias + c);
                v0.x += bb.x; v0.y += bb.y; v1.x += bb.x; v1.y += bb.y;
            }
            if (CVT_OUT) {
                v0.x = __uint_as_float(f2tf32(v0.x));
                v0.y = __uint_as_float(f2tf32(v0.y));
                v1.x = __uint_as_float(f2tf32(v1.x));
                v1.y = __uint_as_float(f2tf32(v1.y));
            }
            *(float2*)(Cm + (size_t)r * Nn + c) = v0;
            *(float2*)(Cm + (size_t)(r + 8) * Nn + c) = v1;
        }
    }
}

// ---------------------------------------------------------------------------
// Flash attention, tf32 mma.sync, cp.async double-buffered K/V.
// 256 threads / 8 warps; each warp owns 16 query rows. Key tiles of 64.
// qkv rows are tf32-rounded. smem words:
//   buf b (b=0,1): K[64][68] @ b*8960, V[64][72] @ b*8960+4352
//   P/Q region @ 17920: 128 rows x 68 (Q staged here, then per-warp P)
// ---------------------------------------------------------------------------
#define KP 68
#define VP 72
#define KVBUFW (64*KP + 64*VP)           // 8960
#define SM_PQ  (2*KVBUFW)                // 17920
#define ATTN_SMEM_BYTES ((SM_PQ + 128*KP) * 4)  // 106496

__global__ __launch_bounds__(256) void attn_mma(const float* __restrict__ qkv,
                                                float* __restrict__ out)
{
    extern __shared__ float sm[];
    uint32_t* smw = (uint32_t*)sm;
    const uint32_t sb = smem_u32(sm);
    const int tid  = threadIdx.x;
    const int wid  = tid >> 5;
    const int lane = tid & 31;
    const int lr   = lane >> 2;
    const int lc   = lane & 3;

    const int bh = blockIdx.y;
    const int b  = bh / HH;
    const int h  = bh % HH;
    const int q0 = blockIdx.x * 128;
    const float* base = qkv + (size_t)b * NN * C3;
    float* Pw = sm + SM_PQ + wid * (16 * KP);

    const int kj  = tid >> 4, kc4 = tid & 15;    // KV loads: 16 rows/iter x 16 f4
    #define ISSUE_KV(kt, buf) do {                                                \
        uint32_t _kb = sb + (buf) * (KVBUFW * 4);                                 \
        uint32_t _vb = _kb + (64 * KP) * 4;                                       \
        _Pragma("unroll")                                                         \
        for (int t = 0; t < 4; t++) {                                             \
            int j = kj + t * 16;                                                  \
            const float* row = base + (size_t)((kt) + j) * C3 + h * HD + kc4 * 4; \
            cp16(_kb + (j * KP + kc4 * 4) * 4, row + CC);                         \
            cp16(_vb + (j * VP + kc4 * 4) * 4, row + 2 * CC);                     \
        }                                                                         \
    } while (0)

    ISSUE_KV(0, 0); cp_commit();

    // stage Q tile [128][64] into the P/Q region (2048 float4)
    #pragma unroll
    for (int t = 0; t < 8; t++) {
        int idx = tid + t * 256;
        int r = idx >> 4, c4 = idx & 15;
        float4 v = *(const float4*)(base + (size_t)(q0 + r) * C3 + h * HD + c4 * 4);
        *(float4*)(sm + SM_PQ + r * KP + c4 * 4) = v;
    }
    __syncthreads();

    uint32_t qf[8][4];
    {
        const float scale = 0.125f;
        int r = wid * 16 + lr;
        #pragma unroll
        for (int kk = 0; kk < 8; kk++) {
            // values are tf32-rounded; *2^-3 is exact -> still valid tf32 bits
            qf[kk][0] = __float_as_uint(sm[SM_PQ + r * KP + kk * 8 + lc] * scale);
            qf[kk][1] = __float_as_uint(sm[SM_PQ + (r + 8) * KP + kk * 8 + lc] * scale);
            qf[kk][2] = __float_as_uint(sm[SM_PQ + r * KP + kk * 8 + lc + 4] * scale);
            qf[kk][3] = __float_as_uint(sm[SM_PQ + (r + 8) * KP + kk * 8 + lc + 4] * scale);
        }
    }

    float of[8][4];
    #pragma unroll
    for (int j = 0; j < 8; j++)
        #pragma unroll
        for (int v = 0; v < 4; v++) of[j][v] = 0.f;
    float m0 = -INFINITY, m1 = -INFINITY, l0 = 0.f, l1 = 0.f;

    for (int it = 0; it < NN / 64; it++) {
        if (it + 1 < NN / 64) {
            ISSUE_KV((it + 1) * 64, (it + 1) & 1); cp_commit();
            cp_wait<1>();
        } else {
            cp_wait<0>();
        }
        __syncthreads();

        const uint32_t* Ks = smw + (it & 1) * KVBUFW;
        const uint32_t* Vs = Ks + 64 * KP;

        // S = Q K^T
        float sf[8][4];
        #pragma unroll
        for (int nt = 0; nt < 8; nt++) {
            #pragma unroll
            for (int v = 0; v < 4; v++) sf[nt][v] = 0.f;
            #pragma unroll
            for (int kk = 0; kk < 8; kk++) {
                uint32_t bf[2];
                bf[0] = Ks[(nt * 8 + lr) * KP + kk * 8 + lc];
                bf[1] = Ks[(nt * 8 + lr) * KP + kk * 8 + lc + 4];
                mma8(sf[nt], qf[kk], bf);
            }
        }

        // online softmax
        float tm0 = -INFINITY, tm1 = -INFINITY;
        #pragma unroll
        for (int nt = 0; nt < 8; nt++) {
            tm0 = fmaxf(tm0, fmaxf(sf[nt][0], sf[nt][1]));
            tm1 = fmaxf(tm1, fmaxf(sf[nt][2], sf[nt][3]));
        }
        tm0 = fmaxf(tm0, __shfl_xor_sync(0xffffffff, tm0, 1));
        tm0 = fmaxf(tm0, __shfl_xor_sync(0xffffffff, tm0, 2));
        tm1 = fmaxf(tm1, __shfl_xor_sync(0xffffffff, tm1, 1));
        tm1 = fmaxf(tm1, __shfl_xor_sync(0xffffffff, tm1, 2));

        float mn0 = fmaxf(m0, tm0), mn1 = fmaxf(m1, tm1);
        float cr0 = __expf(m0 - mn0), cr1 = __expf(m1 - mn1);

        float rs0 = 0.f, rs1 = 0.f;
        #pragma unroll
        for (int nt = 0; nt < 8; nt++) {
            float p00 = __expf(sf[nt][0] - mn0);
            float p01 = __expf(sf[nt][1] - mn0);
            float p10 = __expf(sf[nt][2] - mn1);
            float p11 = __expf(sf[nt][3] - mn1);
            rs0 += p00 + p01;
            rs1 += p10 + p11;
            int c = nt * 8 + 2 * lc;
            *(uint32_t*)&Pw[lr * KP + c]           = f2tf32(p00);
            *(uint32_t*)&Pw[lr * KP + c + 1]       = f2tf32(p01);
            *(uint32_t*)&Pw[(lr + 8) * KP + c]     = f2tf32(p10);
            *(uint32_t*)&Pw[(lr + 8) * KP + c + 1] = f2tf32(p11);
        }
        rs0 += __shfl_xor_sync(0xffffffff, rs0, 1);
        rs0 += __shfl_xor_sync(0xffffffff, rs0, 2);
        rs1 += __shfl_xor_sync(0xffffffff, rs1, 1);
        rs1 += __shfl_xor_sync(0xffffffff, rs1, 2);
        l0 = l0 * cr0 + rs0;
        l1 = l1 * cr1 + rs1;
        m0 = mn0; m1 = mn1;

        #pragma unroll
        for (int dt = 0; dt < 8; dt++) {
            of[dt][0] *= cr0; of[dt][1] *= cr0;
            of[dt][2] *= cr1; of[dt][3] *= cr1;
        }

        __syncwarp();
        // o += P V
        const uint32_t* Pu = (const uint32_t*)Pw;
        #pragma unroll
        for (int kk = 0; kk < 8; kk++) {
            uint32_t pf[4];
            pf[0] = Pu[lr * KP + kk * 8 + lc];
            pf[1] = Pu[(lr + 8) * KP + kk * 8 + lc];
            pf[2] = Pu[lr * KP + kk * 8 + lc + 4];
            pf[3] = Pu[(lr + 8) * KP + kk * 8 + lc + 4];
            #pragma unroll
            for (int dt = 0; dt < 8; dt++) {
                uint32_t bf[2];
                bf[0] = Vs[(kk * 8 + lc) * VP + dt * 8 + lr];
                bf[1] = Vs[(kk * 8 + lc + 4) * VP + dt * 8 + lr];
                mma8(of[dt], pf, bf);
            }
        }
        __syncthreads();
    }
    #undef ISSUE_KV

    // write out, tf32-rounded (proj GEMM consumes raw)
    const float i0 = 1.f / l0, i1 = 1.f / l1;
    const int qr = q0 + wid * 16 + lr;
    #pragma unroll
    for (int dt = 0; dt < 8; dt++) {
        int c = h * HD + dt * 8 + 2 * lc;
        float2 v0, v1;
        v0.x = __uint_as_float(f2tf32(of[dt][0] * i0));
        v0.y = __uint_as_float(f2tf32(of[dt][1] * i0));
        v1.x = __uint_as_float(f2tf32(of[dt][2] * i1));
        v1.y = __uint_as_float(f2tf32(of[dt][3] * i1));
        *(float2*)(out + ((size_t)b * NN + qr) * CC + c) = v0;
        *(float2*)(out + ((size_t)b * NN + qr + 8) * CC + c) = v1;
    }
}

// ---------------------------------------------------------------------------
extern "C" void kernel_launch(void* const* d_in, const int* in_sizes, int n_in,
                              void* d_out, int out_size)
{
    const float* x      = (const float*)d_in[0];
    const float* w_qkv  = (const float*)d_in[1];
    const float* w_proj = (const float*)d_in[2];
    const float* b_proj = (const float*)d_in[3];
    float* out = (float*)d_out;

    float *qkv, *att, *xt, *wqt, *wpt;
    cudaGetSymbolAddress((void**)&qkv, g_qkv);
    cudaGetSymbolAddress((void**)&att, g_att);
    cudaGetSymbolAddress((void**)&xt,  g_xt);
    cudaGetSymbolAddress((void**)&wqt, g_wqt);
    cudaGetSymbolAddress((void**)&wpt, g_wpt);

    static bool attr_done = false;
    if (!attr_done) {
        cudaFuncSetAttribute(attn_mma, cudaFuncAttributeMaxDynamicSharedMemorySize,
                             ATTN_SMEM_BYTES);
        cudaFuncSetAttribute(gemm_cp<false, true>,
                             cudaFuncAttributeMaxDynamicSharedMemorySize, GEMM_SMEM_BYTES);
        cudaFuncSetAttribute(gemm_cp<true, false>,
                             cudaFuncAttributeMaxDynamicSharedMemorySize, GEMM_SMEM_BYTES);
        attr_done = true;
    }

    // 0) tf32 pre-round x, w_qkv, w_proj
    {
        int total = N1 + N2 + N3;
        cvt_pass<<<(total + 255) / 256, 256>>>(x, w_qkv, w_proj);
    }
    // 1) QKV projection (tf32 out)
    {
        dim3 grid(C3 / 128, ROWS / 128);
        gemm_cp<false, true><<<grid, 256, GEMM_SMEM_BYTES>>>(xt, wqt, nullptr, qkv,
                                                             ROWS, CC, C3);
    }
    // 2) attention (tf32 out)
    {
        dim3 grid(NN / 128, BB * HH);
        attn_mma<<<grid, 256, ATTN_SMEM_BYTES>>>(qkv, att);
    }
    // 3) output projection + bias (fp32 out)
    {
        dim3 grid(CC / 128, ROWS / 128);
        gemm_cp<true, false><<<grid, 256, GEMM_SMEM_BYTES>>>(att, wpt, b_proj, out,
                                                             ROWS, CC, CC);
    }
}